// round 7
// baseline (speedup 1.0000x reference)
#include <cuda_runtime.h>
#include <math.h>

#define Bsz  4
#define Lsz  2048
#define Dsz  768
#define Hsz  12
#define HDsz 64
#define Msz  (Bsz * Lsz)

// Scratch (no cudaMalloc allowed) — ~100 MB total
__device__ float g_Q[Bsz * Hsz * Lsz * HDsz];
__device__ float g_K[Bsz * Hsz * Lsz * HDsz];
__device__ float g_V[Bsz * Hsz * Lsz * HDsz];
__device__ float g_O[(size_t)Msz * Dsz];

// ---------------------------------------------------------------------------
// GEMM core with global->register prefetch (software pipeline).
// Computes a 128x128 tile of A[M,768] @ W[768,768] + bias into acc[8][8].
// Loads for k-tile t+1 are issued before the FFMA block of k-tile t, hiding
// global latency behind compute.
// ---------------------------------------------------------------------------
struct GemmRegs { float4 a0, a1, b0, b1; };

__device__ __forceinline__ void gemm_load(
    const float* __restrict__ A, const float* __restrict__ W,
    int m0, int n0, int k0, int tid, GemmRegs& r)
{
    {   // A: thread covers float4s f = tid and tid+256
        int f0 = tid,        f1 = tid + 256;
        r.a0 = *(const float4*)(A + (size_t)(m0 + (f0 >> 2)) * Dsz + k0 + ((f0 & 3) << 2));
        r.a1 = *(const float4*)(A + (size_t)(m0 + (f1 >> 2)) * Dsz + k0 + ((f1 & 3) << 2));
    }
    {   // W: thread covers float4s f = tid and tid+256
        int f0 = tid,        f1 = tid + 256;
        r.b0 = *(const float4*)(W + (size_t)(k0 + (f0 >> 5)) * Dsz + n0 + ((f0 & 31) << 2));
        r.b1 = *(const float4*)(W + (size_t)(k0 + (f1 >> 5)) * Dsz + n0 + ((f1 & 31) << 2));
    }
}

__device__ __forceinline__ void gemm_store_smem(
    float (*As)[128], float (*Bs)[128], int tid, const GemmRegs& r)
{
    {
        int f0 = tid, f1 = tid + 256;
        int row0 = f0 >> 2, kc0 = (f0 & 3) << 2;
        As[kc0 + 0][row0] = r.a0.x; As[kc0 + 1][row0] = r.a0.y;
        As[kc0 + 2][row0] = r.a0.z; As[kc0 + 3][row0] = r.a0.w;
        int row1 = f1 >> 2, kc1 = (f1 & 3) << 2;
        As[kc1 + 0][row1] = r.a1.x; As[kc1 + 1][row1] = r.a1.y;
        As[kc1 + 2][row1] = r.a1.z; As[kc1 + 3][row1] = r.a1.w;
    }
    {
        int f0 = tid, f1 = tid + 256;
        *(float4*)(&Bs[f0 >> 5][(f0 & 31) << 2]) = r.b0;
        *(float4*)(&Bs[f1 >> 5][(f1 & 31) << 2]) = r.b1;
    }
}

__device__ __forceinline__ void gemm_tile(
    const float* __restrict__ A, const float* __restrict__ W,
    int m0, int n0, int tid, int ty, int tx, float acc[8][8])
{
    __shared__ float As[16][128];
    __shared__ float Bs[16][128];

    GemmRegs cur, nxt;
    gemm_load(A, W, m0, n0, 0, tid, cur);

    for (int k0 = 0; k0 < Dsz; k0 += 16) {
        gemm_store_smem(As, Bs, tid, cur);
        __syncthreads();

        if (k0 + 16 < Dsz)
            gemm_load(A, W, m0, n0, k0 + 16, tid, nxt);   // overlaps FFMAs below

#pragma unroll
        for (int kk = 0; kk < 16; kk++) {
            float4 a0 = *(const float4*)(&As[kk][ty * 8]);
            float4 a1 = *(const float4*)(&As[kk][ty * 8 + 4]);
            float4 b0 = *(const float4*)(&Bs[kk][tx * 8]);
            float4 b1 = *(const float4*)(&Bs[kk][tx * 8 + 4]);
            float ra[8] = {a0.x, a0.y, a0.z, a0.w, a1.x, a1.y, a1.z, a1.w};
            float rb[8] = {b0.x, b0.y, b0.z, b0.w, b1.x, b1.y, b1.z, b1.w};
#pragma unroll
            for (int i = 0; i < 8; i++)
#pragma unroll
                for (int j = 0; j < 8; j++)
                    acc[i][j] += ra[i] * rb[j];
        }
        __syncthreads();
        cur = nxt;
    }
}

// ---------------------------------------------------------------------------
// Fused QKV projection: blockIdx.z in {0,1,2} selects Wq/Wk/Wv. Head-split out.
// Grid (6, 64, 3) -> 1152 CTAs (~3.9 full waves at occ 2).
// ---------------------------------------------------------------------------
__global__ void __launch_bounds__(256, 2) qkv_gemm_k(
    const float* __restrict__ A,
    const float* __restrict__ Wq, const float* __restrict__ bq,
    const float* __restrict__ Wk, const float* __restrict__ bk,
    const float* __restrict__ Wv, const float* __restrict__ bv,
    float* __restrict__ outq, float* __restrict__ outk,
    float* __restrict__ outv)
{
    const int z = blockIdx.z;
    const float* W    = (z == 0) ? Wq : (z == 1) ? Wk : Wv;
    const float* bias = (z == 0) ? bq : (z == 1) ? bk : bv;
    float*       out  = (z == 0) ? outq : (z == 1) ? outk : outv;

    const int tid = threadIdx.x;
    const int m0  = blockIdx.y * 128;
    const int n0  = blockIdx.x * 128;
    const int ty  = tid >> 4;
    const int tx  = tid & 15;

    float acc[8][8];
#pragma unroll
    for (int i = 0; i < 8; i++)
#pragma unroll
        for (int j = 0; j < 8; j++) acc[i][j] = 0.f;

    gemm_tile(A, W, m0, n0, tid, ty, tx, acc);

    float bv8[8];
#pragma unroll
    for (int j = 0; j < 8; j++) bv8[j] = bias[n0 + tx * 8 + j];

#pragma unroll
    for (int i = 0; i < 8; i++) {
        int m = m0 + ty * 8 + i;
        float r[8];
#pragma unroll
        for (int j = 0; j < 8; j++) r[j] = acc[i][j] + bv8[j];

        int b = m >> 11;
        int l = m & (Lsz - 1);
        int n = n0 + tx * 8;
        int h = n >> 6;
        int d = n & 63;
        float* dst = out + (((size_t)(b * Hsz + h) * Lsz + l) * HDsz + d);
        ((float4*)dst)[0] = make_float4(r[0], r[1], r[2], r[3]);
        ((float4*)dst)[1] = make_float4(r[4], r[5], r[6], r[7]);
    }
}

// ---------------------------------------------------------------------------
// Output projection GEMM: out[m*768+n] = A @ Wo + bo
// ---------------------------------------------------------------------------
__global__ void __launch_bounds__(256, 2) out_gemm_k(
    const float* __restrict__ A, const float* __restrict__ W,
    const float* __restrict__ bias, float* __restrict__ out)
{
    const int tid = threadIdx.x;
    const int m0  = blockIdx.y * 128;
    const int n0  = blockIdx.x * 128;
    const int ty  = tid >> 4;
    const int tx  = tid & 15;

    float acc[8][8];
#pragma unroll
    for (int i = 0; i < 8; i++)
#pragma unroll
        for (int j = 0; j < 8; j++) acc[i][j] = 0.f;

    gemm_tile(A, W, m0, n0, tid, ty, tx, acc);

    float bv8[8];
#pragma unroll
    for (int j = 0; j < 8; j++) bv8[j] = bias[n0 + tx * 8 + j];

#pragma unroll
    for (int i = 0; i < 8; i++) {
        int m = m0 + ty * 8 + i;
        float r[8];
#pragma unroll
        for (int j = 0; j < 8; j++) r[j] = acc[i][j] + bv8[j];
        float4* p = (float4*)(out + (size_t)m * Dsz + n0 + tx * 8);
        p[0] = make_float4(r[0], r[1], r[2], r[3]);
        p[1] = make_float4(r[4], r[5], r[6], r[7]);
    }
}

// ---------------------------------------------------------------------------
// Flash attention, fp32. Grid (L/64, B*H), 256 threads.
// ---------------------------------------------------------------------------
__device__ __forceinline__ int swz_idx(int d, int rq)  // rq = r>>2 (0..15)
{
    return (d << 6) + (((rq + (d >> 2)) & 15) << 2);
}

__global__ void __launch_bounds__(256, 2) attn_k()
{
    __shared__ float sm[16384];
    float* Qs = sm;            // swizzled [d][r]  4096
    float* Ks = sm + 4096;     // swizzled [d][c]  4096
    float* Vs = sm + 8192;     // natural  [k][v]  4096
    float* Pt = sm + 12288;    // swizzled [k][r]  4096

    const int bh  = blockIdx.y;   // 0..47
    const int qt  = blockIdx.x;   // 0..31
    const int tid = threadIdx.x;
    const int ty  = tid >> 4;     // query group 0..15 (4 rows each)
    const int tx  = tid & 15;     // key/value group 0..15 (4 cols each)

    const float* Qg = g_Q + (size_t)bh * Lsz * HDsz + (size_t)qt * 64 * HDsz;
    const float* Kg = g_K + (size_t)bh * Lsz * HDsz;
    const float* Vg = g_V + (size_t)bh * Lsz * HDsz;

    // Load Q tile transposed+swizzled
#pragma unroll
    for (int i = 0; i < 4; i++) {
        int f  = tid + i * 256;
        int r  = f >> 4;            // 0..63
        int d4 = (f & 15) << 2;     // 0..60
        float4 v = *(const float4*)(Qg + r * HDsz + d4);
        int rq = r >> 2, rr = r & 3;
        Qs[swz_idx(d4 + 0, rq) + rr] = v.x;
        Qs[swz_idx(d4 + 1, rq) + rr] = v.y;
        Qs[swz_idx(d4 + 2, rq) + rr] = v.z;
        Qs[swz_idx(d4 + 3, rq) + rr] = v.w;
    }

    float mrow[4], lrow[4], o[4][4];
#pragma unroll
    for (int i = 0; i < 4; i++) {
        mrow[i] = -INFINITY;
        lrow[i] = 0.f;
#pragma unroll
        for (int j = 0; j < 4; j++) o[i][j] = 0.f;
    }

    const float scale = 0.125f;  // 1/sqrt(64)

    for (int kt = 0; kt < Lsz / 64; kt++) {
        __syncthreads();  // previous-iter consumers of Ks/Vs/Pt done
        // Load K (transposed+swizzled) and V (natural) tiles
#pragma unroll
        for (int i = 0; i < 4; i++) {
            int f  = tid + i * 256;
            int r  = f >> 4;
            int d4 = (f & 15) << 2;
            const float* kp = Kg + (size_t)(kt * 64 + r) * HDsz + d4;
            float4 v = *(const float4*)kp;
            int rq = r >> 2, rr = r & 3;
            Ks[swz_idx(d4 + 0, rq) + rr] = v.x;
            Ks[swz_idx(d4 + 1, rq) + rr] = v.y;
            Ks[swz_idx(d4 + 2, rq) + rr] = v.z;
            Ks[swz_idx(d4 + 3, rq) + rr] = v.w;
            float4 w = *(const float4*)(Vg + (size_t)(kt * 64 + r) * HDsz + d4);
            *(float4*)(Vs + r * 64 + d4) = w;
        }
        __syncthreads();

        // S = Q @ K^T (registers)
        float s[4][4];
#pragma unroll
        for (int i = 0; i < 4; i++)
#pragma unroll
            for (int j = 0; j < 4; j++) s[i][j] = 0.f;

#pragma unroll 16
        for (int d = 0; d < 64; d++) {
            float4 q4 = *(const float4*)(Qs + swz_idx(d, ty));
            float4 k4 = *(const float4*)(Ks + swz_idx(d, tx));
            float qa[4] = {q4.x, q4.y, q4.z, q4.w};
            float ka[4] = {k4.x, k4.y, k4.z, k4.w};
#pragma unroll
            for (int i = 0; i < 4; i++)
#pragma unroll
                for (int j = 0; j < 4; j++)
                    s[i][j] += qa[i] * ka[j];
        }

        // Online softmax update (row stats replicated across the 16 tx lanes)
#pragma unroll
        for (int i = 0; i < 4; i++) {
            float rmax = fmaxf(fmaxf(s[i][0] * scale, s[i][1] * scale),
                               fmaxf(s[i][2] * scale, s[i][3] * scale));
#pragma unroll
            for (int off = 8; off > 0; off >>= 1)
                rmax = fmaxf(rmax, __shfl_xor_sync(0xffffffffu, rmax, off));
            float mnew = fmaxf(mrow[i], rmax);
            float p[4];
            float rsum = 0.f;
#pragma unroll
            for (int j = 0; j < 4; j++) {
                p[j] = __expf(s[i][j] * scale - mnew);
                rsum += p[j];
            }
#pragma unroll
            for (int off = 8; off > 0; off >>= 1)
                rsum += __shfl_xor_sync(0xffffffffu, rsum, off);
            float alpha = __expf(mrow[i] - mnew);
            lrow[i] = lrow[i] * alpha + rsum;
            mrow[i] = mnew;
#pragma unroll
            for (int j = 0; j < 4; j++) {
                o[i][j] *= alpha;
                s[i][j] = p[j];   // reuse s as P
            }
        }

        // Write P transposed+swizzled: Pt[k][r]
#pragma unroll
        for (int j = 0; j < 4; j++) {
            *(float4*)(Pt + swz_idx(tx * 4 + j, ty)) =
                make_float4(s[0][j], s[1][j], s[2][j], s[3][j]);
        }
        __syncthreads();

        // O += P @ V
#pragma unroll 16
        for (int k = 0; k < 64; k++) {
            float4 p4 = *(const float4*)(Pt + swz_idx(k, ty));
            float4 v4 = *(const float4*)(Vs + k * 64 + tx * 4);
            float pa[4] = {p4.x, p4.y, p4.z, p4.w};
            float va[4] = {v4.x, v4.y, v4.z, v4.w};
#pragma unroll
            for (int i = 0; i < 4; i++)
#pragma unroll
                for (int j = 0; j < 4; j++)
                    o[i][j] += pa[i] * va[j];
        }
    }

    // Finalize: O /= l, store as [B, L, H*hd] for the output projection
    const int b = bh / Hsz, h = bh % Hsz;
#pragma unroll
    for (int i = 0; i < 4; i++) {
        float inv = 1.f / lrow[i];
        int q = qt * 64 + ty * 4 + i;
        float4 r4 = make_float4(o[i][0] * inv, o[i][1] * inv,
                                o[i][2] * inv, o[i][3] * inv);
        *(float4*)(g_O + ((size_t)(b * Lsz + q)) * Dsz + h * HDsz + tx * 4) = r4;
    }
}

// ---------------------------------------------------------------------------
extern "C" void kernel_launch(void* const* d_in, const int* in_sizes, int n_in,
                              void* d_out, int out_size)
{
    const float* x  = (const float*)d_in[0];
    const float* Wq = (const float*)d_in[1];
    const float* bq = (const float*)d_in[2];
    const float* Wk = (const float*)d_in[3];
    const float* bk = (const float*)d_in[4];
    const float* Wv = (const float*)d_in[5];
    const float* bv = (const float*)d_in[6];
    const float* Wo = (const float*)d_in[7];
    const float* bo = (const float*)d_in[8];
    float* out = (float*)d_out;

    float *qp, *kp, *vp, *op;
    cudaGetSymbolAddress((void**)&qp, g_Q);
    cudaGetSymbolAddress((void**)&kp, g_K);
    cudaGetSymbolAddress((void**)&vp, g_V);
    cudaGetSymbolAddress((void**)&op, g_O);

    qkv_gemm_k<<<dim3(Dsz / 128, Msz / 128, 3), 256>>>(
        x, Wq, bq, Wk, bk, Wv, bv, qp, kp, vp);

    attn_k<<<dim3(Lsz / 64, Bsz * Hsz), 256>>>();

    out_gemm_k<<<dim3(Dsz / 128, Msz / 128), 256>>>(op, Wo, bo, out);
}

// round 8
// speedup vs baseline: 1.2197x; 1.2197x over previous
#include <cuda_runtime.h>
#include <cuda_bf16.h>
#include <math.h>

#define Bsz  4
#define Lsz  2048
#define Dsz  768
#define Hsz  12
#define HDsz 64
#define Msz  (Bsz * Lsz)
#define DD   (Dsz * Dsz)

typedef __nv_bfloat16 bf16;

// Scratch (no cudaMalloc allowed)
__device__ float g_Q[Bsz * Hsz * Lsz * HDsz];
__device__ float g_K[Bsz * Hsz * Lsz * HDsz];
__device__ float g_V[Bsz * Hsz * Lsz * HDsz];
__device__ float g_O[(size_t)Msz * Dsz];

// split-bf16 operand storage
__device__ bf16 g_xh[(size_t)Msz * Dsz], g_xl[(size_t)Msz * Dsz];
__device__ bf16 g_Oh[(size_t)Msz * Dsz], g_Ol[(size_t)Msz * Dsz];
__device__ bf16 g_Wh[4 * DD], g_Wl[4 * DD];   // Wq, Wk, Wv, Wo

// ---------------------------------------------------------------------------
// Split fp32 -> (hi, lo) bf16.  hi = rn(v), lo = rn(v - hi).  Exact residual.
// ---------------------------------------------------------------------------
__global__ void split_k(const float* __restrict__ in, bf16* __restrict__ hi,
                        bf16* __restrict__ lo, int n)
{
    int i = (blockIdx.x * blockDim.x + threadIdx.x) * 4;
    if (i >= n) return;
    float4 v = *(const float4*)(in + i);
    bf16 h0 = __float2bfloat16(v.x), h1 = __float2bfloat16(v.y);
    bf16 h2 = __float2bfloat16(v.z), h3 = __float2bfloat16(v.w);
    bf16 l0 = __float2bfloat16(v.x - __bfloat162float(h0));
    bf16 l1 = __float2bfloat16(v.y - __bfloat162float(h1));
    bf16 l2 = __float2bfloat16(v.z - __bfloat162float(h2));
    bf16 l3 = __float2bfloat16(v.w - __bfloat162float(h3));
    ((__nv_bfloat162*)(hi + i))[0] = __halves2bfloat162(h0, h1);
    ((__nv_bfloat162*)(hi + i))[1] = __halves2bfloat162(h2, h3);
    ((__nv_bfloat162*)(lo + i))[0] = __halves2bfloat162(l0, l1);
    ((__nv_bfloat162*)(lo + i))[1] = __halves2bfloat162(l2, l3);
}

// ---------------------------------------------------------------------------
// bf16 MMA m16n8k16, fp32 accum
// ---------------------------------------------------------------------------
__device__ __forceinline__ void mma_bf16(float* c, const unsigned* a,
                                         const unsigned* b)
{
    asm volatile(
        "mma.sync.aligned.m16n8k16.row.col.f32.bf16.bf16.f32 "
        "{%0,%1,%2,%3}, {%4,%5,%6,%7}, {%8,%9}, {%0,%1,%2,%3};\n"
        : "+f"(c[0]), "+f"(c[1]), "+f"(c[2]), "+f"(c[3])
        : "r"(a[0]), "r"(a[1]), "r"(a[2]), "r"(a[3]),
          "r"(b[0]), "r"(b[1]));
}

// ---------------------------------------------------------------------------
// Split-bf16 GEMM: out = A @ W + bias, A[M,768], W[768,768].
// C = Ah*Wh + Ah*Wl + Al*Wh (fp32 accum) — ~17-bit effective mantissa.
// Block 128x128, BK=32, 8 warps (warp tile 32m x 64n).
// MODE 0: row-major out.  MODE 1: head-split out.
// blockIdx.z selects among up to 3 (W, bias, out) triples.
// ---------------------------------------------------------------------------
template <int MODE>
__global__ void __launch_bounds__(256, 2) mma_gemm_k(
    const bf16* __restrict__ Ah, const bf16* __restrict__ Al,
    const bf16* __restrict__ Whb, const bf16* __restrict__ Wlb,
    const float* b0p, const float* b1p, const float* b2p,
    float* o0, float* o1, float* o2)
{
    __shared__ bf16 sAh[128][40], sAl[128][40];          // [m][k], padded
    __shared__ unsigned sBh[16][136], sBl[16][136];      // [kpair][n] = (k,k+1)

    const int z = blockIdx.z;
    const bf16* Wh = Whb + (size_t)z * DD;
    const bf16* Wl = Wlb + (size_t)z * DD;
    const float* bias = (z == 0) ? b0p : (z == 1) ? b1p : b2p;
    float* out = (z == 0) ? o0 : (z == 1) ? o1 : o2;

    const int tid  = threadIdx.x;
    const int lane = tid & 31;
    const int wid  = tid >> 5;
    const int wm   = wid & 3;        // 0..3 -> m offset 32*wm
    const int wn   = wid >> 2;       // 0..1 -> n offset 64*wn
    const int m0   = blockIdx.y * 128;
    const int n0   = blockIdx.x * 128;
    const int lr   = lane >> 2;      // 0..7
    const int kq   = (lane & 3) * 2; // 0,2,4,6

    float acc[2][8][4];
#pragma unroll
    for (int mt = 0; mt < 2; mt++)
#pragma unroll
        for (int nt = 0; nt < 8; nt++)
#pragma unroll
            for (int j = 0; j < 4; j++) acc[mt][nt][j] = 0.f;

    for (int k0 = 0; k0 < Dsz; k0 += 32) {
        __syncthreads();   // previous compute reads done
        // --- fill A tiles: thread f -> (m = f/4, k-octet = (f%4)*8)
#pragma unroll
        for (int i = 0; i < 2; i++) {
            int f  = tid + i * 256;
            int m  = f >> 2;
            int k8 = (f & 3) << 3;
            *(uint4*)&sAh[m][k8] =
                *(const uint4*)(Ah + (size_t)(m0 + m) * Dsz + k0 + k8);
            *(uint4*)&sAl[m][k8] =
                *(const uint4*)(Al + (size_t)(m0 + m) * Dsz + k0 + k8);
        }
        // --- fill B tiles k-pair interleaved: thread -> (kp, n-octet)
        {
            int kp  = tid >> 4;           // 0..15
            int n8o = (tid & 15) * 8;     // 0..120
            const bf16* src0 = Wh + (size_t)(k0 + 2 * kp) * Dsz + n0 + n8o;
            uint4 uh = *(const uint4*)src0;
            uint4 vh = *(const uint4*)(src0 + Dsz);
            const bf16* src1 = Wl + (size_t)(k0 + 2 * kp) * Dsz + n0 + n8o;
            uint4 ul = *(const uint4*)src1;
            uint4 vl = *(const uint4*)(src1 + Dsz);
            unsigned wh[8], wl[8];
            const unsigned short* uhs = (const unsigned short*)&uh;
            const unsigned short* vhs = (const unsigned short*)&vh;
            const unsigned short* uls = (const unsigned short*)&ul;
            const unsigned short* vls = (const unsigned short*)&vl;
#pragma unroll
            for (int j = 0; j < 8; j++) {
                wh[j] = (unsigned)uhs[j] | ((unsigned)vhs[j] << 16);
                wl[j] = (unsigned)uls[j] | ((unsigned)vls[j] << 16);
            }
            *(uint4*)&sBh[kp][n8o]     = *(uint4*)&wh[0];
            *(uint4*)&sBh[kp][n8o + 4] = *(uint4*)&wh[4];
            *(uint4*)&sBl[kp][n8o]     = *(uint4*)&wl[0];
            *(uint4*)&sBl[kp][n8o + 4] = *(uint4*)&wl[4];
        }
        __syncthreads();

        // --- compute: two k16 steps
#pragma unroll
        for (int s = 0; s < 2; s++) {
            const int ks = s * 16;
            unsigned ah[2][4], al[2][4];
#pragma unroll
            for (int mt = 0; mt < 2; mt++) {
                int mb = wm * 32 + mt * 16;
                ah[mt][0] = *(const unsigned*)&sAh[mb + lr][ks + kq];
                ah[mt][1] = *(const unsigned*)&sAh[mb + lr + 8][ks + kq];
                ah[mt][2] = *(const unsigned*)&sAh[mb + lr][ks + kq + 8];
                ah[mt][3] = *(const unsigned*)&sAh[mb + lr + 8][ks + kq + 8];
                al[mt][0] = *(const unsigned*)&sAl[mb + lr][ks + kq];
                al[mt][1] = *(const unsigned*)&sAl[mb + lr + 8][ks + kq];
                al[mt][2] = *(const unsigned*)&sAl[mb + lr][ks + kq + 8];
                al[mt][3] = *(const unsigned*)&sAl[mb + lr + 8][ks + kq + 8];
            }
            const int kb = s * 8 + (lane & 3);  // k-pair index
#pragma unroll
            for (int nt = 0; nt < 8; nt++) {
                int nn = wn * 64 + nt * 8 + lr;
                unsigned bh[2], bl[2];
                bh[0] = sBh[kb][nn];     bh[1] = sBh[kb + 4][nn];
                bl[0] = sBl[kb][nn];     bl[1] = sBl[kb + 4][nn];
#pragma unroll
                for (int mt = 0; mt < 2; mt++) {
                    mma_bf16(acc[mt][nt], ah[mt], bh);
                    mma_bf16(acc[mt][nt], ah[mt], bl);
                    mma_bf16(acc[mt][nt], al[mt], bh);
                }
            }
        }
    }

    // --- epilogue
#pragma unroll
    for (int mt = 0; mt < 2; mt++) {
#pragma unroll
        for (int nt = 0; nt < 8; nt++) {
            int m = m0 + wm * 32 + mt * 16 + lr;
            int n = n0 + wn * 64 + nt * 8 + kq;
            float bv0 = bias[n], bv1 = bias[n + 1];
            float2 r0 = make_float2(acc[mt][nt][0] + bv0, acc[mt][nt][1] + bv1);
            float2 r1 = make_float2(acc[mt][nt][2] + bv0, acc[mt][nt][3] + bv1);
            if (MODE == 0) {
                *(float2*)(out + (size_t)m * Dsz + n) = r0;
                *(float2*)(out + (size_t)(m + 8) * Dsz + n) = r1;
            } else {
                int b = m >> 11, l = m & (Lsz - 1);
                int h = n >> 6,  d = n & 63;
                size_t base = ((size_t)(b * Hsz + h) * Lsz + l) * HDsz + d;
                *(float2*)(out + base) = r0;
                *(float2*)(out + base + 8 * HDsz) = r1;
            }
        }
    }
}

// ---------------------------------------------------------------------------
// Flash attention, fp32 (unchanged from R7 — proven: rel_err 1.19e-6).
// ---------------------------------------------------------------------------
__device__ __forceinline__ int swz_idx(int d, int rq)
{
    return (d << 6) + (((rq + (d >> 2)) & 15) << 2);
}

__global__ void __launch_bounds__(256, 2) attn_k()
{
    __shared__ float sm[16384];
    float* Qs = sm;
    float* Ks = sm + 4096;
    float* Vs = sm + 8192;
    float* Pt = sm + 12288;

    const int bh  = blockIdx.y;
    const int qt  = blockIdx.x;
    const int tid = threadIdx.x;
    const int ty  = tid >> 4;
    const int tx  = tid & 15;

    const float* Qg = g_Q + (size_t)bh * Lsz * HDsz + (size_t)qt * 64 * HDsz;
    const float* Kg = g_K + (size_t)bh * Lsz * HDsz;
    const float* Vg = g_V + (size_t)bh * Lsz * HDsz;

#pragma unroll
    for (int i = 0; i < 4; i++) {
        int f  = tid + i * 256;
        int r  = f >> 4;
        int d4 = (f & 15) << 2;
        float4 v = *(const float4*)(Qg + r * HDsz + d4);
        int rq = r >> 2, rr = r & 3;
        Qs[swz_idx(d4 + 0, rq) + rr] = v.x;
        Qs[swz_idx(d4 + 1, rq) + rr] = v.y;
        Qs[swz_idx(d4 + 2, rq) + rr] = v.z;
        Qs[swz_idx(d4 + 3, rq) + rr] = v.w;
    }

    float mrow[4], lrow[4], o[4][4];
#pragma unroll
    for (int i = 0; i < 4; i++) {
        mrow[i] = -INFINITY;
        lrow[i] = 0.f;
#pragma unroll
        for (int j = 0; j < 4; j++) o[i][j] = 0.f;
    }

    const float scale = 0.125f;

    for (int kt = 0; kt < Lsz / 64; kt++) {
        __syncthreads();
#pragma unroll
        for (int i = 0; i < 4; i++) {
            int f  = tid + i * 256;
            int r  = f >> 4;
            int d4 = (f & 15) << 2;
            const float* kp = Kg + (size_t)(kt * 64 + r) * HDsz + d4;
            float4 v = *(const float4*)kp;
            int rq = r >> 2, rr = r & 3;
            Ks[swz_idx(d4 + 0, rq) + rr] = v.x;
            Ks[swz_idx(d4 + 1, rq) + rr] = v.y;
            Ks[swz_idx(d4 + 2, rq) + rr] = v.z;
            Ks[swz_idx(d4 + 3, rq) + rr] = v.w;
            float4 w = *(const float4*)(Vg + (size_t)(kt * 64 + r) * HDsz + d4);
            *(float4*)(Vs + r * 64 + d4) = w;
        }
        __syncthreads();

        float s[4][4];
#pragma unroll
        for (int i = 0; i < 4; i++)
#pragma unroll
            for (int j = 0; j < 4; j++) s[i][j] = 0.f;

#pragma unroll 16
        for (int d = 0; d < 64; d++) {
            float4 q4 = *(const float4*)(Qs + swz_idx(d, ty));
            float4 k4 = *(const float4*)(Ks + swz_idx(d, tx));
            float qa[4] = {q4.x, q4.y, q4.z, q4.w};
            float ka[4] = {k4.x, k4.y, k4.z, k4.w};
#pragma unroll
            for (int i = 0; i < 4; i++)
#pragma unroll
                for (int j = 0; j < 4; j++)
                    s[i][j] += qa[i] * ka[j];
        }

#pragma unroll
        for (int i = 0; i < 4; i++) {
            float rmax = fmaxf(fmaxf(s[i][0] * scale, s[i][1] * scale),
                               fmaxf(s[i][2] * scale, s[i][3] * scale));
#pragma unroll
            for (int off = 8; off > 0; off >>= 1)
                rmax = fmaxf(rmax, __shfl_xor_sync(0xffffffffu, rmax, off));
            float mnew = fmaxf(mrow[i], rmax);
            float p[4];
            float rsum = 0.f;
#pragma unroll
            for (int j = 0; j < 4; j++) {
                p[j] = __expf(s[i][j] * scale - mnew);
                rsum += p[j];
            }
#pragma unroll
            for (int off = 8; off > 0; off >>= 1)
                rsum += __shfl_xor_sync(0xffffffffu, rsum, off);
            float alpha = __expf(mrow[i] - mnew);
            lrow[i] = lrow[i] * alpha + rsum;
            mrow[i] = mnew;
#pragma unroll
            for (int j = 0; j < 4; j++) {
                o[i][j] *= alpha;
                s[i][j] = p[j];
            }
        }

#pragma unroll
        for (int j = 0; j < 4; j++) {
            *(float4*)(Pt + swz_idx(tx * 4 + j, ty)) =
                make_float4(s[0][j], s[1][j], s[2][j], s[3][j]);
        }
        __syncthreads();

#pragma unroll 16
        for (int k = 0; k < 64; k++) {
            float4 p4 = *(const float4*)(Pt + swz_idx(k, ty));
            float4 v4 = *(const float4*)(Vs + k * 64 + tx * 4);
            float pa[4] = {p4.x, p4.y, p4.z, p4.w};
            float va[4] = {v4.x, v4.y, v4.z, v4.w};
#pragma unroll
            for (int i = 0; i < 4; i++)
#pragma unroll
                for (int j = 0; j < 4; j++)
                    o[i][j] += pa[i] * va[j];
        }
    }

    const int b = bh / Hsz, h = bh % Hsz;
#pragma unroll
    for (int i = 0; i < 4; i++) {
        float inv = 1.f / lrow[i];
        int q = qt * 64 + ty * 4 + i;
        float4 r4 = make_float4(o[i][0] * inv, o[i][1] * inv,
                                o[i][2] * inv, o[i][3] * inv);
        *(float4*)(g_O + ((size_t)(b * Lsz + q)) * Dsz + h * HDsz + tx * 4) = r4;
    }
}

// ---------------------------------------------------------------------------
extern "C" void kernel_launch(void* const* d_in, const int* in_sizes, int n_in,
                              void* d_out, int out_size)
{
    const float* x  = (const float*)d_in[0];
    const float* Wq = (const float*)d_in[1];
    const float* bq = (const float*)d_in[2];
    const float* Wk = (const float*)d_in[3];
    const float* bk = (const float*)d_in[4];
    const float* Wv = (const float*)d_in[5];
    const float* bv = (const float*)d_in[6];
    const float* Wo = (const float*)d_in[7];
    const float* bo = (const float*)d_in[8];
    float* out = (float*)d_out;

    float *qp, *kp, *vp, *op;
    cudaGetSymbolAddress((void**)&qp, g_Q);
    cudaGetSymbolAddress((void**)&kp, g_K);
    cudaGetSymbolAddress((void**)&vp, g_V);
    cudaGetSymbolAddress((void**)&op, g_O);
    bf16 *xh, *xl, *oh, *ol, *wh, *wl;
    cudaGetSymbolAddress((void**)&xh, g_xh);
    cudaGetSymbolAddress((void**)&xl, g_xl);
    cudaGetSymbolAddress((void**)&oh, g_Oh);
    cudaGetSymbolAddress((void**)&ol, g_Ol);
    cudaGetSymbolAddress((void**)&wh, g_Wh);
    cudaGetSymbolAddress((void**)&wl, g_Wl);

    const int nX = Msz * Dsz;
    split_k<<<(nX / 4 + 255) / 256, 256>>>(x, xh, xl, nX);
    split_k<<<(DD / 4 + 255) / 256, 256>>>(Wq, wh + 0 * DD, wl + 0 * DD, DD);
    split_k<<<(DD / 4 + 255) / 256, 256>>>(Wk, wh + 1 * DD, wl + 1 * DD, DD);
    split_k<<<(DD / 4 + 255) / 256, 256>>>(Wv, wh + 2 * DD, wl + 2 * DD, DD);
    split_k<<<(DD / 4 + 255) / 256, 256>>>(Wo, wh + 3 * DD, wl + 3 * DD, DD);

    // Fused QKV projections on tensor cores
    mma_gemm_k<1><<<dim3(Dsz / 128, Msz / 128, 3), 256>>>(
        xh, xl, wh, wl, bq, bk, bv, qp, kp, vp);

    attn_k<<<dim3(Lsz / 64, Bsz * Hsz), 256>>>();

    split_k<<<(nX / 4 + 255) / 256, 256>>>(op, oh, ol, nX);
    mma_gemm_k<0><<<dim3(Dsz / 128, Msz / 128, 1), 256>>>(
        oh, ol, wh + 3 * DD, wl + 3 * DD, bo, bo, bo, out, out, out);
}

// round 10
// speedup vs baseline: 2.4101x; 1.9760x over previous
#include <cuda_runtime.h>
#include <cuda_bf16.h>
#include <math.h>

#define Bsz  4
#define Lsz  2048
#define Dsz  768
#define Hsz  12
#define HDsz 64
#define Msz  (Bsz * Lsz)
#define DD   (Dsz * Dsz)

typedef __nv_bfloat16 bf16;

// Scratch (no cudaMalloc allowed)
__device__ float g_Q[Bsz * Hsz * Lsz * HDsz];
__device__ float g_K[Bsz * Hsz * Lsz * HDsz];
__device__ float g_V[Bsz * Hsz * Lsz * HDsz];

// split-bf16 operand storage
__device__ bf16 g_xh[(size_t)Msz * Dsz], g_xl[(size_t)Msz * Dsz];
__device__ bf16 g_Oh[(size_t)Msz * Dsz], g_Ol[(size_t)Msz * Dsz];
__device__ bf16 g_Wh[4 * DD], g_Wl[4 * DD];   // Wq, Wk, Wv, Wo

// ---------------------------------------------------------------------------
__global__ void split_k(const float* __restrict__ in, bf16* __restrict__ hi,
                        bf16* __restrict__ lo, int n)
{
    int i = (blockIdx.x * blockDim.x + threadIdx.x) * 4;
    if (i >= n) return;
    float4 v = *(const float4*)(in + i);
    bf16 h0 = __float2bfloat16(v.x), h1 = __float2bfloat16(v.y);
    bf16 h2 = __float2bfloat16(v.z), h3 = __float2bfloat16(v.w);
    bf16 l0 = __float2bfloat16(v.x - __bfloat162float(h0));
    bf16 l1 = __float2bfloat16(v.y - __bfloat162float(h1));
    bf16 l2 = __float2bfloat16(v.z - __bfloat162float(h2));
    bf16 l3 = __float2bfloat16(v.w - __bfloat162float(h3));
    ((__nv_bfloat162*)(hi + i))[0] = __halves2bfloat162(h0, h1);
    ((__nv_bfloat162*)(hi + i))[1] = __halves2bfloat162(h2, h3);
    ((__nv_bfloat162*)(lo + i))[0] = __halves2bfloat162(l0, l1);
    ((__nv_bfloat162*)(lo + i))[1] = __halves2bfloat162(l2, l3);
}

// ---------------------------------------------------------------------------
__device__ __forceinline__ void mma_bf16(float* c, const unsigned* a,
                                         const unsigned* b)
{
    asm volatile(
        "mma.sync.aligned.m16n8k16.row.col.f32.bf16.bf16.f32 "
        "{%0,%1,%2,%3}, {%4,%5,%6,%7}, {%8,%9}, {%0,%1,%2,%3};\n"
        : "+f"(c[0]), "+f"(c[1]), "+f"(c[2]), "+f"(c[3])
        : "r"(a[0]), "r"(a[1]), "r"(a[2]), "r"(a[3]),
          "r"(b[0]), "r"(b[1]));
}

__device__ __forceinline__ void ldsm_x4(unsigned* r, const void* p)
{
    unsigned a = (unsigned)__cvta_generic_to_shared(p);
    asm volatile("ldmatrix.sync.aligned.m8n8.x4.shared.b16 {%0,%1,%2,%3}, [%4];"
                 : "=r"(r[0]), "=r"(r[1]), "=r"(r[2]), "=r"(r[3]) : "r"(a));
}

__device__ __forceinline__ void ldsm_x4_t(unsigned* r, const void* p)
{
    unsigned a = (unsigned)__cvta_generic_to_shared(p);
    asm volatile("ldmatrix.sync.aligned.m8n8.x4.trans.shared.b16 {%0,%1,%2,%3}, [%4];"
                 : "=r"(r[0]), "=r"(r[1]), "=r"(r[2]), "=r"(r[3]) : "r"(a));
}

__device__ __forceinline__ unsigned pack2(float a, float b)
{
    __nv_bfloat162 t = __floats2bfloat162_rn(a, b);   // a in low half
    return *(unsigned*)&t;
}

// ---------------------------------------------------------------------------
// Split-bf16 GEMM (validated R8): C = Ah*Wh + Ah*Wl + Al*Wh, fp32 accum.
// ---------------------------------------------------------------------------
template <int MODE>
__global__ void __launch_bounds__(256, 2) mma_gemm_k(
    const bf16* __restrict__ Ah, const bf16* __restrict__ Al,
    const bf16* __restrict__ Whb, const bf16* __restrict__ Wlb,
    const float* b0p, const float* b1p, const float* b2p,
    float* o0, float* o1, float* o2)
{
    __shared__ bf16 sAh[128][40], sAl[128][40];
    __shared__ unsigned sBh[16][136], sBl[16][136];

    const int z = blockIdx.z;
    const bf16* Wh = Whb + (size_t)z * DD;
    const bf16* Wl = Wlb + (size_t)z * DD;
    const float* bias = (z == 0) ? b0p : (z == 1) ? b1p : b2p;
    float* out = (z == 0) ? o0 : (z == 1) ? o1 : o2;

    const int tid  = threadIdx.x;
    const int lane = tid & 31;
    const int wid  = tid >> 5;
    const int wm   = wid & 3;
    const int wn   = wid >> 2;
    const int m0   = blockIdx.y * 128;
    const int n0   = blockIdx.x * 128;
    const int lr   = lane >> 2;
    const int kq   = (lane & 3) * 2;

    float acc[2][8][4];
#pragma unroll
    for (int mt = 0; mt < 2; mt++)
#pragma unroll
        for (int nt = 0; nt < 8; nt++)
#pragma unroll
            for (int j = 0; j < 4; j++) acc[mt][nt][j] = 0.f;

    for (int k0 = 0; k0 < Dsz; k0 += 32) {
        __syncthreads();
#pragma unroll
        for (int i = 0; i < 2; i++) {
            int f  = tid + i * 256;
            int m  = f >> 2;
            int k8 = (f & 3) << 3;
            *(uint4*)&sAh[m][k8] =
                *(const uint4*)(Ah + (size_t)(m0 + m) * Dsz + k0 + k8);
            *(uint4*)&sAl[m][k8] =
                *(const uint4*)(Al + (size_t)(m0 + m) * Dsz + k0 + k8);
        }
        {
            int kp  = tid >> 4;
            int n8o = (tid & 15) * 8;
            const bf16* src0 = Wh + (size_t)(k0 + 2 * kp) * Dsz + n0 + n8o;
            uint4 uh = *(const uint4*)src0;
            uint4 vh = *(const uint4*)(src0 + Dsz);
            const bf16* src1 = Wl + (size_t)(k0 + 2 * kp) * Dsz + n0 + n8o;
            uint4 ul = *(const uint4*)src1;
            uint4 vl = *(const uint4*)(src1 + Dsz);
            unsigned wh[8], wl[8];
            const unsigned short* uhs = (const unsigned short*)&uh;
            const unsigned short* vhs = (const unsigned short*)&vh;
            const unsigned short* uls = (const unsigned short*)&ul;
            const unsigned short* vls = (const unsigned short*)&vl;
#pragma unroll
            for (int j = 0; j < 8; j++) {
                wh[j] = (unsigned)uhs[j] | ((unsigned)vhs[j] << 16);
                wl[j] = (unsigned)uls[j] | ((unsigned)vls[j] << 16);
            }
            *(uint4*)&sBh[kp][n8o]     = *(uint4*)&wh[0];
            *(uint4*)&sBh[kp][n8o + 4] = *(uint4*)&wh[4];
            *(uint4*)&sBl[kp][n8o]     = *(uint4*)&wl[0];
            *(uint4*)&sBl[kp][n8o + 4] = *(uint4*)&wl[4];
        }
        __syncthreads();

#pragma unroll
        for (int s = 0; s < 2; s++) {
            const int ks = s * 16;
            unsigned ah[2][4], al[2][4];
#pragma unroll
            for (int mt = 0; mt < 2; mt++) {
                int mb = wm * 32 + mt * 16;
                ah[mt][0] = *(const unsigned*)&sAh[mb + lr][ks + kq];
                ah[mt][1] = *(const unsigned*)&sAh[mb + lr + 8][ks + kq];
                ah[mt][2] = *(const unsigned*)&sAh[mb + lr][ks + kq + 8];
                ah[mt][3] = *(const unsigned*)&sAh[mb + lr + 8][ks + kq + 8];
                al[mt][0] = *(const unsigned*)&sAl[mb + lr][ks + kq];
                al[mt][1] = *(const unsigned*)&sAl[mb + lr + 8][ks + kq];
                al[mt][2] = *(const unsigned*)&sAl[mb + lr][ks + kq + 8];
                al[mt][3] = *(const unsigned*)&sAl[mb + lr + 8][ks + kq + 8];
            }
            const int kb = s * 8 + (lane & 3);
#pragma unroll
            for (int nt = 0; nt < 8; nt++) {
                int nn = wn * 64 + nt * 8 + lr;
                unsigned bh[2], bl[2];
                bh[0] = sBh[kb][nn];     bh[1] = sBh[kb + 4][nn];
                bl[0] = sBl[kb][nn];     bl[1] = sBl[kb + 4][nn];
#pragma unroll
                for (int mt = 0; mt < 2; mt++) {
                    mma_bf16(acc[mt][nt], ah[mt], bh);
                    mma_bf16(acc[mt][nt], ah[mt], bl);
                    mma_bf16(acc[mt][nt], al[mt], bh);
                }
            }
        }
    }

#pragma unroll
    for (int mt = 0; mt < 2; mt++) {
#pragma unroll
        for (int nt = 0; nt < 8; nt++) {
            int m = m0 + wm * 32 + mt * 16 + lr;
            int n = n0 + wn * 64 + nt * 8 + kq;
            float bv0 = bias[n], bv1 = bias[n + 1];
            float2 r0 = make_float2(acc[mt][nt][0] + bv0, acc[mt][nt][1] + bv1);
            float2 r1 = make_float2(acc[mt][nt][2] + bv0, acc[mt][nt][3] + bv1);
            if (MODE == 0) {
                *(float2*)(out + (size_t)m * Dsz + n) = r0;
                *(float2*)(out + (size_t)(m + 8) * Dsz + n) = r1;
            } else {
                int b = m >> 11, l = m & (Lsz - 1);
                int h = n >> 6,  d = n & 63;
                size_t base = ((size_t)(b * Hsz + h) * Lsz + l) * HDsz + d;
                *(float2*)(out + base) = r0;
                *(float2*)(out + base + 8 * HDsz) = r1;
            }
        }
    }
}

// ---------------------------------------------------------------------------
// Tensor-core flash attention, split-bf16 (3-MMA) for both QK^T and PV.
// 128 threads = 4 warps; block: 64 queries, streamed 64-key tiles.
// Each warp owns 16 query rows. Epilogue writes split-bf16 straight into
// the output-projection's A operand (g_Oh/g_Ol), layout [B*L][H*64].
// ---------------------------------------------------------------------------
__global__ void __launch_bounds__(128) attn_mma_k()
{
    __shared__ bf16 sKh[64][72], sKl[64][72];   // also used to stage Q
    __shared__ bf16 sVh[64][72], sVl[64][72];

    const int bh   = blockIdx.y;          // 0..47
    const int qt   = blockIdx.x;          // 0..31
    const int tid  = threadIdx.x;
    const int lane = tid & 31;
    const int wid  = tid >> 5;            // 0..3
    const int band = wid * 16;            // warp's query-row band
    const int lr   = lane >> 2;           // 0..7
    const int lc2  = (lane & 3) * 2;      // 0,2,4,6

    const float* Qg = g_Q + (size_t)bh * Lsz * HDsz + (size_t)qt * 64 * HDsz;
    const float* Kg = g_K + (size_t)bh * Lsz * HDsz;
    const float* Vg = g_V + (size_t)bh * Lsz * HDsz;

    // --- stage Q (pre-scaled by 1/sqrt(hd)) into sK arrays, split ---
#pragma unroll
    for (int i = 0; i < 8; i++) {
        int f  = tid + i * 128;
        int r  = f >> 4;
        int d4 = (f & 15) << 2;
        float4 v = *(const float4*)(Qg + r * HDsz + d4);
        v.x *= 0.125f; v.y *= 0.125f; v.z *= 0.125f; v.w *= 0.125f;
        bf16 h0 = __float2bfloat16(v.x), h1 = __float2bfloat16(v.y);
        bf16 h2 = __float2bfloat16(v.z), h3 = __float2bfloat16(v.w);
        unsigned hp0 = pack2(v.x, v.y);
        unsigned hp1 = pack2(v.z, v.w);
        unsigned lp0 = pack2(v.x - __bfloat162float(h0), v.y - __bfloat162float(h1));
        unsigned lp1 = pack2(v.z - __bfloat162float(h2), v.w - __bfloat162float(h3));
        *(uint2*)&sKh[r][d4] = make_uint2(hp0, hp1);
        *(uint2*)&sKl[r][d4] = make_uint2(lp0, lp1);
    }
    __syncthreads();

    // --- Q A-fragments (held in registers for the whole kernel) ---
    unsigned qh[4][4], ql[4][4];
#pragma unroll
    for (int ks = 0; ks < 4; ks++) {
        int row = band + (lane & 15);
        int col = ks * 16 + (lane >> 4) * 8;
        ldsm_x4(qh[ks], &sKh[row][col]);
        ldsm_x4(ql[ks], &sKl[row][col]);
    }

    float accO[8][4];
#pragma unroll
    for (int nt = 0; nt < 8; nt++)
#pragma unroll
        for (int j = 0; j < 4; j++) accO[nt][j] = 0.f;
    float m0 = -INFINITY, m1 = -INFINITY, l0 = 0.f, l1 = 0.f;

    for (int kt = 0; kt < Lsz / 64; kt++) {
        __syncthreads();   // prior S/PV reads of sK/sV complete
        // --- load + split K,V tiles ---
#pragma unroll
        for (int i = 0; i < 8; i++) {
            int f  = tid + i * 128;
            int r  = f >> 4;
            int d4 = (f & 15) << 2;
            const float* kp = Kg + (size_t)(kt * 64 + r) * HDsz + d4;
            float4 kv = *(const float4*)kp;
            bf16 h0 = __float2bfloat16(kv.x), h1 = __float2bfloat16(kv.y);
            bf16 h2 = __float2bfloat16(kv.z), h3 = __float2bfloat16(kv.w);
            *(uint2*)&sKh[r][d4] = make_uint2(pack2(kv.x, kv.y), pack2(kv.z, kv.w));
            *(uint2*)&sKl[r][d4] = make_uint2(
                pack2(kv.x - __bfloat162float(h0), kv.y - __bfloat162float(h1)),
                pack2(kv.z - __bfloat162float(h2), kv.w - __bfloat162float(h3)));
            const float* vp = Vg + (size_t)(kt * 64 + r) * HDsz + d4;
            float4 vv = *(const float4*)vp;
            bf16 g0 = __float2bfloat16(vv.x), g1 = __float2bfloat16(vv.y);
            bf16 g2 = __float2bfloat16(vv.z), g3 = __float2bfloat16(vv.w);
            *(uint2*)&sVh[r][d4] = make_uint2(pack2(vv.x, vv.y), pack2(vv.z, vv.w));
            *(uint2*)&sVl[r][d4] = make_uint2(
                pack2(vv.x - __bfloat162float(g0), vv.y - __bfloat162float(g1)),
                pack2(vv.z - __bfloat162float(g2), vv.w - __bfloat162float(g3)));
        }
        __syncthreads();

        // --- S = Q K^T (split, 3 MMAs per fragment) ---
        float s[8][4];
#pragma unroll
        for (int nt = 0; nt < 8; nt++)
#pragma unroll
            for (int j = 0; j < 4; j++) s[nt][j] = 0.f;

#pragma unroll
        for (int kp = 0; kp < 2; kp++) {
#pragma unroll
            for (int nt = 0; nt < 8; nt++) {
                int key = nt * 8 + (lane & 7);
                int col = kp * 32 + (lane >> 3) * 8;
                unsigned bh4[4], bl4[4];
                ldsm_x4(bh4, &sKh[key][col]);
                ldsm_x4(bl4, &sKl[key][col]);
                mma_bf16(s[nt], qh[2 * kp],     &bh4[0]);
                mma_bf16(s[nt], qh[2 * kp],     &bl4[0]);
                mma_bf16(s[nt], ql[2 * kp],     &bh4[0]);
                mma_bf16(s[nt], qh[2 * kp + 1], &bh4[2]);
                mma_bf16(s[nt], qh[2 * kp + 1], &bl4[2]);
                mma_bf16(s[nt], ql[2 * kp + 1], &bh4[2]);
            }
        }

        // --- online softmax on C fragments (rows r=band+lr and r+8) ---
        float mx0 = -INFINITY, mx1 = -INFINITY;
#pragma unroll
        for (int nt = 0; nt < 8; nt++) {
            mx0 = fmaxf(mx0, fmaxf(s[nt][0], s[nt][1]));
            mx1 = fmaxf(mx1, fmaxf(s[nt][2], s[nt][3]));
        }
        mx0 = fmaxf(mx0, __shfl_xor_sync(0xffffffffu, mx0, 1));
        mx0 = fmaxf(mx0, __shfl_xor_sync(0xffffffffu, mx0, 2));
        mx1 = fmaxf(mx1, __shfl_xor_sync(0xffffffffu, mx1, 1));
        mx1 = fmaxf(mx1, __shfl_xor_sync(0xffffffffu, mx1, 2));
        float mn0 = fmaxf(m0, mx0), mn1 = fmaxf(m1, mx1);
        float a0 = __expf(m0 - mn0), a1 = __expf(m1 - mn1);
        float sum0 = 0.f, sum1 = 0.f;
#pragma unroll
        for (int nt = 0; nt < 8; nt++) {
            s[nt][0] = __expf(s[nt][0] - mn0);
            s[nt][1] = __expf(s[nt][1] - mn0);
            s[nt][2] = __expf(s[nt][2] - mn1);
            s[nt][3] = __expf(s[nt][3] - mn1);
            sum0 += s[nt][0] + s[nt][1];
            sum1 += s[nt][2] + s[nt][3];
        }
        sum0 += __shfl_xor_sync(0xffffffffu, sum0, 1);
        sum0 += __shfl_xor_sync(0xffffffffu, sum0, 2);
        sum1 += __shfl_xor_sync(0xffffffffu, sum1, 1);
        sum1 += __shfl_xor_sync(0xffffffffu, sum1, 2);
        l0 = l0 * a0 + sum0;  m0 = mn0;
        l1 = l1 * a1 + sum1;  m1 = mn1;
#pragma unroll
        for (int nt = 0; nt < 8; nt++) {
            accO[nt][0] *= a0;  accO[nt][1] *= a0;
            accO[nt][2] *= a1;  accO[nt][3] *= a1;
        }

        // --- O += P V (P from C-frags, split; V via ldmatrix.trans) ---
#pragma unroll
        for (int ks = 0; ks < 4; ks++) {
            unsigned ph[4], pl[4];
            {
                float p00 = s[2*ks][0],   p01 = s[2*ks][1];
                float p02 = s[2*ks][2],   p03 = s[2*ks][3];
                float p10 = s[2*ks+1][0], p11 = s[2*ks+1][1];
                float p12 = s[2*ks+1][2], p13 = s[2*ks+1][3];
                ph[0] = pack2(p00, p01);  ph[1] = pack2(p02, p03);
                ph[2] = pack2(p10, p11);  ph[3] = pack2(p12, p13);
                bf16 h;
                h = __float2bfloat16(p00); float r00 = p00 - __bfloat162float(h);
                h = __float2bfloat16(p01); float r01 = p01 - __bfloat162float(h);
                h = __float2bfloat16(p02); float r02 = p02 - __bfloat162float(h);
                h = __float2bfloat16(p03); float r03 = p03 - __bfloat162float(h);
                h = __float2bfloat16(p10); float r10 = p10 - __bfloat162float(h);
                h = __float2bfloat16(p11); float r11 = p11 - __bfloat162float(h);
                h = __float2bfloat16(p12); float r12 = p12 - __bfloat162float(h);
                h = __float2bfloat16(p13); float r13 = p13 - __bfloat162float(h);
                pl[0] = pack2(r00, r01);  pl[1] = pack2(r02, r03);
                pl[2] = pack2(r10, r11);  pl[3] = pack2(r12, r13);
            }
#pragma unroll
            for (int np = 0; np < 4; np++) {
                int row = ks * 16 + (lane & 15);
                int col = np * 16 + (lane >> 4) * 8;
                unsigned vh4[4], vl4[4];
                ldsm_x4_t(vh4, &sVh[row][col]);
                ldsm_x4_t(vl4, &sVl[row][col]);
                mma_bf16(accO[2 * np],     ph, &vh4[0]);
                mma_bf16(accO[2 * np],     ph, &vl4[0]);
                mma_bf16(accO[2 * np],     pl, &vh4[0]);
                mma_bf16(accO[2 * np + 1], ph, &vh4[2]);
                mma_bf16(accO[2 * np + 1], ph, &vl4[2]);
                mma_bf16(accO[2 * np + 1], pl, &vh4[2]);
            }
        }
    }

    // --- epilogue: normalize, split, write to out-proj A operand ---
    const float inv0 = 1.f / l0, inv1 = 1.f / l1;
    const int b = bh / Hsz, h = bh % Hsz;
    const int q0 = qt * 64 + band + lr;
#pragma unroll
    for (int nt = 0; nt < 8; nt++) {
        int d = nt * 8 + lc2;
        size_t base0 = ((size_t)(b * Lsz + q0)) * Dsz + h * HDsz + d;
        size_t base1 = ((size_t)(b * Lsz + q0 + 8)) * Dsz + h * HDsz + d;
        float o0 = accO[nt][0] * inv0, o1 = accO[nt][1] * inv0;
        float o2 = accO[nt][2] * inv1, o3 = accO[nt][3] * inv1;
        bf16 h0 = __float2bfloat16(o0), h1 = __float2bfloat16(o1);
        bf16 h2 = __float2bfloat16(o2), h3 = __float2bfloat16(o3);
        *(unsigned*)(g_Oh + base0) = pack2(o0, o1);
        *(unsigned*)(g_Oh + base1) = pack2(o2, o3);
        *(unsigned*)(g_Ol + base0) =
            pack2(o0 - __bfloat162float(h0), o1 - __bfloat162float(h1));
        *(unsigned*)(g_Ol + base1) =
            pack2(o2 - __bfloat162float(h2), o3 - __bfloat162float(h3));
    }
}

// ---------------------------------------------------------------------------
extern "C" void kernel_launch(void* const* d_in, const int* in_sizes, int n_in,
                              void* d_out, int out_size)
{
    const float* x  = (const float*)d_in[0];
    const float* Wq = (const float*)d_in[1];
    const float* bq = (const float*)d_in[2];
    const float* Wk = (const float*)d_in[3];
    const float* bk = (const float*)d_in[4];
    const float* Wv = (const float*)d_in[5];
    const float* bv = (const float*)d_in[6];
    const float* Wo = (const float*)d_in[7];
    const float* bo = (const float*)d_in[8];
    float* out = (float*)d_out;

    float *qp, *kp, *vp;
    cudaGetSymbolAddress((void**)&qp, g_Q);
    cudaGetSymbolAddress((void**)&kp, g_K);
    cudaGetSymbolAddress((void**)&vp, g_V);
    bf16 *xh, *xl, *oh, *ol, *wh, *wl;
    cudaGetSymbolAddress((void**)&xh, g_xh);
    cudaGetSymbolAddress((void**)&xl, g_xl);
    cudaGetSymbolAddress((void**)&oh, g_Oh);
    cudaGetSymbolAddress((void**)&ol, g_Ol);
    cudaGetSymbolAddress((void**)&wh, g_Wh);
    cudaGetSymbolAddress((void**)&wl, g_Wl);

    const int nX = Msz * Dsz;
    split_k<<<(nX / 4 + 255) / 256, 256>>>(x, xh, xl, nX);
    split_k<<<(DD / 4 + 255) / 256, 256>>>(Wq, wh + 0 * DD, wl + 0 * DD, DD);
    split_k<<<(DD / 4 + 255) / 256, 256>>>(Wk, wh + 1 * DD, wl + 1 * DD, DD);
    split_k<<<(DD / 4 + 255) / 256, 256>>>(Wv, wh + 2 * DD, wl + 2 * DD, DD);
    split_k<<<(DD / 4 + 255) / 256, 256>>>(Wo, wh + 3 * DD, wl + 3 * DD, DD);

    mma_gemm_k<1><<<dim3(Dsz / 128, Msz / 128, 3), 256>>>(
        xh, xl, wh, wl, bq, bk, bv, qp, kp, vp);

    attn_mma_k<<<dim3(Lsz / 64, Bsz * Hsz), 128>>>();

    mma_gemm_k<0><<<dim3(Dsz / 128, Msz / 128, 1), 256>>>(
        oh, ol, wh + 3 * DD, wl + 3 * DD, bo, bo, bo, out, out, out);
}